// round 10
// baseline (speedup 1.0000x reference)
#include <cuda_runtime.h>

// Problem constants
#define BATCH 32
#define IMG_H 480
#define IMG_W 640
#define OUT_H 470
#define OUT_W 630
#define WS    11

// Tiling: 32 wide x 60 tall
#define TILE_W 32
#define TILE_H 60
#define IN_W   (TILE_W + WS - 1)   // 42
#define IN_W_PAD 44                // float2 slots per row (alignment pad; cols 42,43 never read)
#define IN_H   (TILE_H + WS - 1)   // 70
#define MID_W  TILE_W              // 32

#define GX 20   // ceil(630/32)
#define GY 8    // ceil(470/60) -> covers 480 rows
#define NBLOCKS (GX * GY * BATCH)  // 5120
#define NTHREADS 512
#define N_STRIPS3 ((TILE_H / 4) * TILE_W)   // 480 vertical strips

// Normalized 1D Gaussian, sigma=1.5, ws=11 (symmetric)
static __device__ __forceinline__ float gw(int t) {
    constexpr float w[11] = {
        0.00102839f, 0.00759866f, 0.03600077f, 0.10936124f, 0.21300553f,
        0.26601172f,
        0.21300553f, 0.10936124f, 0.03600077f, 0.00759866f, 0.00102839f
    };
    return w[t];
}

__device__ float        g_partials[NBLOCKS];
__device__ unsigned int g_count = 0;

__global__ __launch_bounds__(NTHREADS, 3)
void ssim_tile_kernel(const float* __restrict__ img1,
                      const float* __restrict__ img2,
                      float* __restrict__ out)
{
    extern __shared__ float smem[];
    float2* s_sd  = (float2*)smem;                         // IN_H * IN_W_PAD  (s,d) pairs
    float4* s_mid = (float4*)(s_sd + IN_H * IN_W_PAD);     // IN_H * MID_W (Ms,Md,Es,Ed)

    __shared__ float    s_red[NTHREADS / 32];
    __shared__ unsigned s_flag;

    const int tid = threadIdx.x;
    const int bz  = blockIdx.z;
    const int r0  = blockIdx.y * TILE_H;
    const int c0  = blockIdx.x * TILE_W;

    const float* im1 = img1 + (size_t)bz * IMG_H * IMG_W;
    const float* im2 = img2 + (size_t)bz * IMG_H * IMG_W;

    // ---- Stage 1: load tile (halo), store interleaved (s,d) = (x+y, x-y) ----
    if (c0 + IN_W_PAD <= IMG_W && r0 + IN_H <= IMG_H) {
        // fast path: float4 gmem loads (c0 multiple of 32, IMG_W multiple of 4)
        const int NQ = IN_W_PAD / 4;   // 11 quads per row
        for (int i = tid; i < IN_H * NQ; i += NTHREADS) {
            int r = i / NQ;
            int q = i - r * NQ;
            const float4* p1 = (const float4*)(im1 + (size_t)(r0 + r) * IMG_W + c0) + q;
            const float4* p2 = (const float4*)(im2 + (size_t)(r0 + r) * IMG_W + c0) + q;
            float4 a = *p1;
            float4 b = *p2;
            float4* dst = (float4*)(s_sd + r * IN_W_PAD + q * 4);
            dst[0] = make_float4(a.x + b.x, a.x - b.x, a.y + b.y, a.y - b.y);
            dst[1] = make_float4(a.z + b.z, a.z - b.z, a.w + b.w, a.w - b.w);
        }
    } else {
        for (int i = tid; i < IN_H * IN_W_PAD; i += NTHREADS) {
            int r = i / IN_W_PAD;
            int c = i - r * IN_W_PAD;
            int gr = r0 + r;
            int gc = c0 + c;
            float v1 = 0.f, v2 = 0.f;
            if (gr < IMG_H && gc < IMG_W) {
                int idx = gr * IMG_W + gc;
                v1 = im1[idx];
                v2 = im2[idx];
            }
            s_sd[r * IN_W_PAD + c] = make_float2(v1 + v2, v1 - v2);
        }
    }
    __syncthreads();

    // ---- Stage 2: horizontal conv, 4 channels (s, d, s^2, d^2), 4-wide strips ----
    // 560 strips (70 rows x 8 quads); 7 x LDS.128 per strip, zero waste.
    for (int st = tid; st < IN_H * (TILE_W / 4); st += NTHREADS) {
        int row = st >> 3;            // st / 8
        int cq  = (st & 7) << 2;      // (st % 8) * 4

        // 14 (s,d) pairs = 7 float4 loads (byte offset cq*8: 32B-aligned)
        const float4* p4 = (const float4*)(s_sd + row * IN_W_PAD + cq);
        float sv[14], dv[14];
        #pragma unroll
        for (int i = 0; i < 7; i++) {
            float4 v = p4[i];
            sv[2*i+0] = v.x; dv[2*i+0] = v.y;
            sv[2*i+1] = v.z; dv[2*i+1] = v.w;
        }

        float aMs[4] = {0.f, 0.f, 0.f, 0.f};
        float aMd[4] = {0.f, 0.f, 0.f, 0.f};
        float aEs[4] = {0.f, 0.f, 0.f, 0.f};
        float aEd[4] = {0.f, 0.f, 0.f, 0.f};

        #pragma unroll
        for (int k = 0; k < WS + 3; k++) {   // 14 taps serve 4 outputs
            float skv = sv[k];
            float dkv = dv[k];
            float ss  = skv * skv;
            float dd  = dkv * dkv;
            #pragma unroll
            for (int o = 0; o < 4; o++) {
                int t = k - o;
                if (t >= 0 && t < WS) {      // compile-time resolved
                    float w = gw(t);         // literal -> FFMA-imm (rt=1)
                    aMs[o] = fmaf(w, skv, aMs[o]);
                    aMd[o] = fmaf(w, dkv, aMd[o]);
                    aEs[o] = fmaf(w, ss,  aEs[o]);
                    aEd[o] = fmaf(w, dd,  aEd[o]);
                }
            }
        }
        float4* m = s_mid + row * MID_W + cq;
        #pragma unroll
        for (int o = 0; o < 4; o++)
            m[o] = make_float4(aMs[o], aMd[o], aEs[o], aEd[o]);  // STS.128
    }
    __syncthreads();

    // ---- Stage 3: vertical conv + SSIM + local sum; 480 strips ----
    const float C1 = 1.0f;   // (0.01*100)^2
    const float C2 = 9.0f;   // (0.03*100)^2
    float lsum = 0.f;

    if (tid < N_STRIPS3) {
        int c  = tid & (TILE_W - 1);
        int rq = (tid >> 5) << 2;

        float Ms[4] = {0.f, 0.f, 0.f, 0.f};
        float Md[4] = {0.f, 0.f, 0.f, 0.f};
        float Es[4] = {0.f, 0.f, 0.f, 0.f};
        float Ed[4] = {0.f, 0.f, 0.f, 0.f};

        #pragma unroll
        for (int k = 0; k < WS + 3; k++) {
            float4 v = s_mid[(rq + k) * MID_W + c];   // one LDS.128 per tap
            #pragma unroll
            for (int o = 0; o < 4; o++) {
                int t = k - o;
                if (t >= 0 && t < WS) {
                    float w = gw(t);
                    Ms[o] = fmaf(w, v.x, Ms[o]);
                    Md[o] = fmaf(w, v.y, Md[o]);
                    Es[o] = fmaf(w, v.z, Es[o]);
                    Ed[o] = fmaf(w, v.w, Ed[o]);
                }
            }
        }

        int gc = c0 + c;
        if (gc < OUT_W) {
            #pragma unroll
            for (int o = 0; o < 4; o++) {
                int gr = r0 + rq + o;
                if (gr < OUT_H) {
                    float ms = Ms[o], md = Md[o];
                    float ms2 = ms * ms;
                    float md2 = md * md;
                    float Ps = Es[o] - ms2;     // s1+s2+2*s12
                    float Qd = Ed[o] - md2;     // s1+s2-2*s12
                    float v1 = 0.5f * (Ps - Qd) + C2;            // 2*s12 + C2
                    float v2 = 0.5f * (Ps + Qd) + C2;            // s1+s2 + C2
                    float num = (0.5f * (ms2 - md2) + C1) * v1;  // (2*mu12+C1)*v1
                    float den = (0.5f * (ms2 + md2) + C1) * v2;  // (mu1^2+mu2^2+C1)*v2
                    lsum += __fdividef(num, den);
                }
            }
        }
    }

    // ---- Stage 4: block partial + fused last-block finalize ----
    #pragma unroll
    for (int off = 16; off > 0; off >>= 1)
        lsum += __shfl_down_sync(0xffffffffu, lsum, off);

    int warp = tid >> 5;
    int lane = tid & 31;
    if (lane == 0) s_red[warp] = lsum;
    __syncthreads();
    if (tid == 0) {
        float t = 0.f;
        #pragma unroll
        for (int i = 0; i < NTHREADS / 32; i++) t += s_red[i];
        int bidx = (blockIdx.z * GY + blockIdx.y) * GX + blockIdx.x;
        g_partials[bidx] = t;
        __threadfence();
        unsigned v = atomicAdd(&g_count, 1u);
        s_flag = (v == (unsigned)(NBLOCKS - 1));
    }
    __syncthreads();

    if (s_flag) {
        // deterministic: fixed summation order independent of which block runs this
        float acc = 0.f;
        for (int i = tid; i < NBLOCKS; i += NTHREADS)
            acc += __ldcg(&g_partials[i]);
        #pragma unroll
        for (int off = 16; off > 0; off >>= 1)
            acc += __shfl_down_sync(0xffffffffu, acc, off);
        if (lane == 0) s_red[warp] = acc;
        __syncthreads();
        if (tid == 0) {
            float tt = 0.f;
            #pragma unroll
            for (int i = 0; i < NTHREADS / 32; i++) tt += s_red[i];
            float mean = tt * (1.0f / ((float)BATCH * OUT_H * OUT_W));
            out[0] = (1.0f - mean) * 0.5f;
            g_count = 0;   // reset for next graph replay
        }
    }
}

extern "C" void kernel_launch(void* const* d_in, const int* in_sizes, int n_in,
                              void* d_out, int out_size)
{
    const float* img1 = (const float*)d_in[0];
    const float* img2 = (const float*)d_in[1];
    float* out = (float*)d_out;

    size_t smem_bytes = (size_t)(IN_H * IN_W_PAD) * sizeof(float2)
                      + (size_t)(IN_H * MID_W) * sizeof(float4);
    cudaFuncSetAttribute(ssim_tile_kernel,
                         cudaFuncAttributeMaxDynamicSharedMemorySize,
                         (int)smem_bytes);

    dim3 grid(GX, GY, BATCH);
    ssim_tile_kernel<<<grid, NTHREADS, smem_bytes>>>(img1, img2, out);
}

// round 11
// speedup vs baseline: 1.0995x; 1.0995x over previous
#include <cuda_runtime.h>

// Problem constants
#define BATCH 32
#define IMG_H 480
#define IMG_W 640
#define OUT_H 470
#define OUT_W 630
#define WS    11

// Tiling: 32 wide x 60 tall (8 row-bands cover 480 exactly: no padded band)
#define TILE_W 32
#define TILE_H 60
#define IN_W   (TILE_W + WS - 1)   // 42
#define IN_W_PAD 44                // multiple of 4 for float4 loads
#define IN_H   (TILE_H + WS - 1)   // 70
#define MID_W  TILE_W              // 32

#define GX 20   // ceil(630/32)
#define GY 8    // 8 * 60 = 480 rows
#define NBLOCKS (GX * GY * BATCH)  // 5120
#define NTHREADS 512
#define N_STRIPS3 ((TILE_H / 4) * TILE_W)   // 480 vertical strips

// Normalized 1D Gaussian, sigma=1.5, ws=11 (symmetric)
static __device__ __forceinline__ float gw(int t) {
    constexpr float w[11] = {
        0.00102839f, 0.00759866f, 0.03600077f, 0.10936124f, 0.21300553f,
        0.26601172f,
        0.21300553f, 0.10936124f, 0.03600077f, 0.00759866f, 0.00102839f
    };
    return w[t];
}

__device__ float        g_partials[NBLOCKS];
__device__ unsigned int g_count = 0;

__global__ __launch_bounds__(NTHREADS, 3)
void ssim_tile_kernel(const float* __restrict__ img1,
                      const float* __restrict__ img2,
                      float* __restrict__ out)
{
    extern __shared__ float smem[];
    // Separate s/d arrays: stage-2 lane access is consecutive 16B -> conflict-free
    float*  s_s   = smem;                                  // IN_H * IN_W_PAD  (x+y)
    float*  s_d   = s_s + IN_H * IN_W_PAD;                 // IN_H * IN_W_PAD  (x-y)
    float4* s_mid = (float4*)(s_d + IN_H * IN_W_PAD);      // IN_H * MID_W (Ms,Md,Es,Ed)

    __shared__ float    s_red[NTHREADS / 32];
    __shared__ unsigned s_flag;

    const int tid = threadIdx.x;
    const int bz  = blockIdx.z;
    const int r0  = blockIdx.y * TILE_H;
    const int c0  = blockIdx.x * TILE_W;

    const float* im1 = img1 + (size_t)bz * IMG_H * IMG_W;
    const float* im2 = img2 + (size_t)bz * IMG_H * IMG_W;

    // ---- Stage 1: load tile (with halo), store s=x+y, d=x-y ----
    if (c0 + IN_W_PAD <= IMG_W && r0 + IN_H <= IMG_H) {
        // fast path: interior block, float4 loads (row start 16B-aligned:
        // c0 multiple of 32, IMG_W multiple of 4)
        const int NQ = IN_W_PAD / 4;   // 11 quads per row
        for (int i = tid; i < IN_H * NQ; i += NTHREADS) {
            int r = i / NQ;
            int q = i - r * NQ;
            const float4* p1 = (const float4*)(im1 + (size_t)(r0 + r) * IMG_W + c0) + q;
            const float4* p2 = (const float4*)(im2 + (size_t)(r0 + r) * IMG_W + c0) + q;
            float4 a = *p1;
            float4 b = *p2;
            float4 sv = make_float4(a.x + b.x, a.y + b.y, a.z + b.z, a.w + b.w);
            float4 dv = make_float4(a.x - b.x, a.y - b.y, a.z - b.z, a.w - b.w);
            ((float4*)(s_s + r * IN_W_PAD))[q] = sv;
            ((float4*)(s_d + r * IN_W_PAD))[q] = dv;
        }
    } else {
        for (int i = tid; i < IN_H * IN_W_PAD; i += NTHREADS) {
            int r = i / IN_W_PAD;
            int c = i - r * IN_W_PAD;
            int gr = r0 + r;
            int gc = c0 + c;
            float v1 = 0.f, v2 = 0.f;
            if (gr < IMG_H && gc < IMG_W) {
                int idx = gr * IMG_W + gc;
                v1 = im1[idx];
                v2 = im2[idx];
            }
            s_s[r * IN_W_PAD + c] = v1 + v2;
            s_d[r * IN_W_PAD + c] = v1 - v2;
        }
    }
    __syncthreads();

    // ---- Stage 2: horizontal conv, 4 channels (s, d, s^2, d^2), 4-wide strips ----
    // 560 strips (70 rows x 8 quads); float4 smem loads (cq mult of 4).
    for (int st = tid; st < IN_H * (TILE_W / 4); st += NTHREADS) {
        int row = st >> 3;            // st / 8
        int cq  = (st & 7) << 2;      // (st % 8) * 4

        const float4* ps4 = (const float4*)(s_s + row * IN_W_PAD + cq);
        const float4* pd4 = (const float4*)(s_d + row * IN_W_PAD + cq);
        float sv[16], dv[16];
        #pragma unroll
        for (int i = 0; i < 4; i++) {
            float4 a = ps4[i];
            float4 b = pd4[i];
            sv[4*i+0] = a.x; sv[4*i+1] = a.y; sv[4*i+2] = a.z; sv[4*i+3] = a.w;
            dv[4*i+0] = b.x; dv[4*i+1] = b.y; dv[4*i+2] = b.z; dv[4*i+3] = b.w;
        }

        float aMs[4] = {0.f, 0.f, 0.f, 0.f};
        float aMd[4] = {0.f, 0.f, 0.f, 0.f};
        float aEs[4] = {0.f, 0.f, 0.f, 0.f};
        float aEd[4] = {0.f, 0.f, 0.f, 0.f};

        #pragma unroll
        for (int k = 0; k < WS + 3; k++) {   // 14 taps serve 4 outputs
            float skv = sv[k];
            float dkv = dv[k];
            float ss  = skv * skv;
            float dd  = dkv * dkv;
            #pragma unroll
            for (int o = 0; o < 4; o++) {
                int t = k - o;
                if (t >= 0 && t < WS) {      // compile-time resolved
                    float w = gw(t);         // literal -> FFMA-imm (rt=1)
                    aMs[o] = fmaf(w, skv, aMs[o]);
                    aMd[o] = fmaf(w, dkv, aMd[o]);
                    aEs[o] = fmaf(w, ss,  aEs[o]);
                    aEd[o] = fmaf(w, dd,  aEd[o]);
                }
            }
        }
        float4* m = s_mid + row * MID_W + cq;
        #pragma unroll
        for (int o = 0; o < 4; o++)
            m[o] = make_float4(aMs[o], aMd[o], aEs[o], aEd[o]);  // STS.128
    }
    __syncthreads();

    // ---- Stage 3: vertical conv + SSIM + local sum; 480 strips ----
    const float C1 = 1.0f;   // (0.01*100)^2
    const float C2 = 9.0f;   // (0.03*100)^2
    float lsum = 0.f;

    if (tid < N_STRIPS3) {
        int c  = tid & (TILE_W - 1);
        int rq = (tid >> 5) << 2;

        float Ms[4] = {0.f, 0.f, 0.f, 0.f};
        float Md[4] = {0.f, 0.f, 0.f, 0.f};
        float Es[4] = {0.f, 0.f, 0.f, 0.f};
        float Ed[4] = {0.f, 0.f, 0.f, 0.f};

        #pragma unroll
        for (int k = 0; k < WS + 3; k++) {
            float4 v = s_mid[(rq + k) * MID_W + c];   // one LDS.128 per tap
            #pragma unroll
            for (int o = 0; o < 4; o++) {
                int t = k - o;
                if (t >= 0 && t < WS) {
                    float w = gw(t);
                    Ms[o] = fmaf(w, v.x, Ms[o]);
                    Md[o] = fmaf(w, v.y, Md[o]);
                    Es[o] = fmaf(w, v.z, Es[o]);
                    Ed[o] = fmaf(w, v.w, Ed[o]);
                }
            }
        }

        int gc = c0 + c;
        if (gc < OUT_W) {
            #pragma unroll
            for (int o = 0; o < 4; o++) {
                int gr = r0 + rq + o;
                if (gr < OUT_H) {
                    float ms = Ms[o], md = Md[o];
                    float ms2 = ms * ms;
                    float md2 = md * md;
                    float Ps = Es[o] - ms2;     // s1+s2+2*s12
                    float Qd = Ed[o] - md2;     // s1+s2-2*s12
                    float v1 = 0.5f * (Ps - Qd) + C2;            // 2*s12 + C2
                    float v2 = 0.5f * (Ps + Qd) + C2;            // s1+s2 + C2
                    float num = (0.5f * (ms2 - md2) + C1) * v1;  // (2*mu12+C1)*v1
                    float den = (0.5f * (ms2 + md2) + C1) * v2;  // (mu1^2+mu2^2+C1)*v2
                    lsum += __fdividef(num, den);
                }
            }
        }
    }

    // ---- Stage 4: block partial + fused last-block finalize ----
    #pragma unroll
    for (int off = 16; off > 0; off >>= 1)
        lsum += __shfl_down_sync(0xffffffffu, lsum, off);

    int warp = tid >> 5;
    int lane = tid & 31;
    if (lane == 0) s_red[warp] = lsum;
    __syncthreads();
    if (tid == 0) {
        float t = 0.f;
        #pragma unroll
        for (int i = 0; i < NTHREADS / 32; i++) t += s_red[i];
        int bidx = (blockIdx.z * GY + blockIdx.y) * GX + blockIdx.x;
        g_partials[bidx] = t;
        __threadfence();
        unsigned v = atomicAdd(&g_count, 1u);
        s_flag = (v == (unsigned)(NBLOCKS - 1));
    }
    __syncthreads();

    if (s_flag) {
        // deterministic: fixed summation order independent of which block runs this
        float acc = 0.f;
        for (int i = tid; i < NBLOCKS; i += NTHREADS)
            acc += __ldcg(&g_partials[i]);
        #pragma unroll
        for (int off = 16; off > 0; off >>= 1)
            acc += __shfl_down_sync(0xffffffffu, acc, off);
        if (lane == 0) s_red[warp] = acc;
        __syncthreads();
        if (tid == 0) {
            float tt = 0.f;
            #pragma unroll
            for (int i = 0; i < NTHREADS / 32; i++) tt += s_red[i];
            float mean = tt * (1.0f / ((float)BATCH * OUT_H * OUT_W));
            out[0] = (1.0f - mean) * 0.5f;
            g_count = 0;   // reset for next graph replay
        }
    }
}

extern "C" void kernel_launch(void* const* d_in, const int* in_sizes, int n_in,
                              void* d_out, int out_size)
{
    const float* img1 = (const float*)d_in[0];
    const float* img2 = (const float*)d_in[1];
    float* out = (float*)d_out;

    size_t smem_bytes = (size_t)(2 * IN_H * IN_W_PAD) * sizeof(float)
                      + (size_t)(IN_H * MID_W) * sizeof(float4);
    cudaFuncSetAttribute(ssim_tile_kernel,
                         cudaFuncAttributeMaxDynamicSharedMemorySize,
                         (int)smem_bytes);

    dim3 grid(GX, GY, BATCH);
    ssim_tile_kernel<<<grid, NTHREADS, smem_bytes>>>(img1, img2, out);
}

// round 12
// speedup vs baseline: 1.1310x; 1.0287x over previous
#include <cuda_runtime.h>

// Problem constants
#define BATCH 32
#define IMG_H 480
#define IMG_W 640
#define OUT_H 470
#define OUT_W 630
#define WS    11

// Tiling: 32 wide x 120 tall (4 row-bands cover 480 exactly)
#define TILE_W 32
#define TILE_H 120
#define IN_W   (TILE_W + WS - 1)   // 42
#define IN_W_PAD 44                // multiple of 4 for float4 loads
#define IN_H   (TILE_H + WS - 1)   // 130
#define MID_W  TILE_W              // 32

#define GX 20   // ceil(630/32)
#define GY 4    // 4 * 120 = 480 rows
#define NBLOCKS (GX * GY * BATCH)  // 2560
#define NTHREADS 512

#define H3 8                                 // stage-3 strip height
#define N_STRIPS3 ((TILE_H / H3) * TILE_W)   // 480 vertical strips

// Normalized 1D Gaussian, sigma=1.5, ws=11 (symmetric)
static __device__ __forceinline__ float gw(int t) {
    constexpr float w[11] = {
        0.00102839f, 0.00759866f, 0.03600077f, 0.10936124f, 0.21300553f,
        0.26601172f,
        0.21300553f, 0.10936124f, 0.03600077f, 0.00759866f, 0.00102839f
    };
    return w[t];
}

__device__ float        g_partials[NBLOCKS];
__device__ unsigned int g_count = 0;

__global__ __launch_bounds__(NTHREADS, 2)
void ssim_tile_kernel(const float* __restrict__ img1,
                      const float* __restrict__ img2,
                      float* __restrict__ out)
{
    extern __shared__ float smem[];
    // Separate s/d arrays: stage-2 lane access is consecutive 16B -> conflict-free
    float*  s_s   = smem;                                  // IN_H * IN_W_PAD  (x+y)
    float*  s_d   = s_s + IN_H * IN_W_PAD;                 // IN_H * IN_W_PAD  (x-y)
    float4* s_mid = (float4*)(s_d + IN_H * IN_W_PAD);      // IN_H * MID_W (Ms,Md,Es,Ed)

    __shared__ float    s_red[NTHREADS / 32];
    __shared__ unsigned s_flag;

    const int tid = threadIdx.x;
    const int bz  = blockIdx.z;
    const int r0  = blockIdx.y * TILE_H;
    const int c0  = blockIdx.x * TILE_W;

    const float* im1 = img1 + (size_t)bz * IMG_H * IMG_W;
    const float* im2 = img2 + (size_t)bz * IMG_H * IMG_W;

    // ---- Stage 1: load tile (with halo), store s=x+y, d=x-y ----
    if (c0 + IN_W_PAD <= IMG_W) {
        // quad path: full-width rows (c0 mult of 32, IMG_W mult of 4 -> 16B aligned);
        // bottom-band blocks get per-row guard, OOB rows -> 0
        const int NQ = IN_W_PAD / 4;   // 11 quads per row
        for (int i = tid; i < IN_H * NQ; i += NTHREADS) {
            int r = i / NQ;
            int q = i - r * NQ;
            int gr = r0 + r;
            float4 a = make_float4(0.f, 0.f, 0.f, 0.f);
            float4 b = a;
            if (gr < IMG_H) {
                a = ((const float4*)(im1 + (size_t)gr * IMG_W + c0))[q];
                b = ((const float4*)(im2 + (size_t)gr * IMG_W + c0))[q];
            }
            float4 sv = make_float4(a.x + b.x, a.y + b.y, a.z + b.z, a.w + b.w);
            float4 dv = make_float4(a.x - b.x, a.y - b.y, a.z - b.z, a.w - b.w);
            ((float4*)(s_s + r * IN_W_PAD))[q] = sv;
            ((float4*)(s_d + r * IN_W_PAD))[q] = dv;
        }
    } else {
        // right-edge blocks (bx = GX-1): scalar guarded path
        for (int i = tid; i < IN_H * IN_W_PAD; i += NTHREADS) {
            int r = i / IN_W_PAD;
            int c = i - r * IN_W_PAD;
            int gr = r0 + r;
            int gc = c0 + c;
            float v1 = 0.f, v2 = 0.f;
            if (gr < IMG_H && gc < IMG_W) {
                int idx = gr * IMG_W + gc;
                v1 = im1[idx];
                v2 = im2[idx];
            }
            s_s[r * IN_W_PAD + c] = v1 + v2;
            s_d[r * IN_W_PAD + c] = v1 - v2;
        }
    }
    __syncthreads();

    // ---- Stage 2: horizontal conv, 4 channels (s, d, s^2, d^2), 4-wide strips ----
    // 1040 strips (130 rows x 8 quads); float4 smem loads (cq mult of 4).
    for (int st = tid; st < IN_H * (TILE_W / 4); st += NTHREADS) {
        int row = st >> 3;            // st / 8
        int cq  = (st & 7) << 2;      // (st % 8) * 4

        const float4* ps4 = (const float4*)(s_s + row * IN_W_PAD + cq);
        const float4* pd4 = (const float4*)(s_d + row * IN_W_PAD + cq);
        float sv[16], dv[16];
        #pragma unroll
        for (int i = 0; i < 4; i++) {
            float4 a = ps4[i];
            float4 b = pd4[i];
            sv[4*i+0] = a.x; sv[4*i+1] = a.y; sv[4*i+2] = a.z; sv[4*i+3] = a.w;
            dv[4*i+0] = b.x; dv[4*i+1] = b.y; dv[4*i+2] = b.z; dv[4*i+3] = b.w;
        }

        float aMs[4] = {0.f, 0.f, 0.f, 0.f};
        float aMd[4] = {0.f, 0.f, 0.f, 0.f};
        float aEs[4] = {0.f, 0.f, 0.f, 0.f};
        float aEd[4] = {0.f, 0.f, 0.f, 0.f};

        #pragma unroll
        for (int k = 0; k < WS + 3; k++) {   // 14 taps serve 4 outputs
            float skv = sv[k];
            float dkv = dv[k];
            float ss  = skv * skv;
            float dd  = dkv * dkv;
            #pragma unroll
            for (int o = 0; o < 4; o++) {
                int t = k - o;
                if (t >= 0 && t < WS) {      // compile-time resolved
                    float w = gw(t);         // literal -> FFMA-imm (rt=1)
                    aMs[o] = fmaf(w, skv, aMs[o]);
                    aMd[o] = fmaf(w, dkv, aMd[o]);
                    aEs[o] = fmaf(w, ss,  aEs[o]);
                    aEd[o] = fmaf(w, dd,  aEd[o]);
                }
            }
        }
        float4* m = s_mid + row * MID_W + cq;
        #pragma unroll
        for (int o = 0; o < 4; o++)
            m[o] = make_float4(aMs[o], aMd[o], aEs[o], aEd[o]);  // STS.128
    }
    __syncthreads();

    // ---- Stage 3: vertical conv + SSIM + local sum; 8-tall strips ----
    // 480 strips: 18 taps serve 8 outputs (2.25 LDS.128/output).
    const float C1 = 1.0f;   // (0.01*100)^2
    const float C2 = 9.0f;   // (0.03*100)^2
    float lsum = 0.f;

    if (tid < N_STRIPS3) {
        int c  = tid & (TILE_W - 1);
        int rq = (tid >> 5) * H3;

        float Ms[H3] = {0.f, 0.f, 0.f, 0.f, 0.f, 0.f, 0.f, 0.f};
        float Md[H3] = {0.f, 0.f, 0.f, 0.f, 0.f, 0.f, 0.f, 0.f};
        float Es[H3] = {0.f, 0.f, 0.f, 0.f, 0.f, 0.f, 0.f, 0.f};
        float Ed[H3] = {0.f, 0.f, 0.f, 0.f, 0.f, 0.f, 0.f, 0.f};

        #pragma unroll
        for (int k = 0; k < WS + H3 - 1; k++) {   // 18 taps
            float4 v = s_mid[(rq + k) * MID_W + c];   // one LDS.128 per tap
            #pragma unroll
            for (int o = 0; o < H3; o++) {
                int t = k - o;
                if (t >= 0 && t < WS) {
                    float w = gw(t);
                    Ms[o] = fmaf(w, v.x, Ms[o]);
                    Md[o] = fmaf(w, v.y, Md[o]);
                    Es[o] = fmaf(w, v.z, Es[o]);
                    Ed[o] = fmaf(w, v.w, Ed[o]);
                }
            }
        }

        int gc = c0 + c;
        if (gc < OUT_W) {
            #pragma unroll
            for (int o = 0; o < H3; o++) {
                int gr = r0 + rq + o;
                if (gr < OUT_H) {
                    float ms = Ms[o], md = Md[o];
                    float ms2 = ms * ms;
                    float md2 = md * md;
                    float Ps = Es[o] - ms2;     // s1+s2+2*s12
                    float Qd = Ed[o] - md2;     // s1+s2-2*s12
                    float v1 = 0.5f * (Ps - Qd) + C2;            // 2*s12 + C2
                    float v2 = 0.5f * (Ps + Qd) + C2;            // s1+s2 + C2
                    float num = (0.5f * (ms2 - md2) + C1) * v1;  // (2*mu12+C1)*v1
                    float den = (0.5f * (ms2 + md2) + C1) * v2;  // (mu1^2+mu2^2+C1)*v2
                    lsum += __fdividef(num, den);
                }
            }
        }
    }

    // ---- Stage 4: block partial + fused last-block finalize ----
    #pragma unroll
    for (int off = 16; off > 0; off >>= 1)
        lsum += __shfl_down_sync(0xffffffffu, lsum, off);

    int warp = tid >> 5;
    int lane = tid & 31;
    if (lane == 0) s_red[warp] = lsum;
    __syncthreads();
    if (tid == 0) {
        float t = 0.f;
        #pragma unroll
        for (int i = 0; i < NTHREADS / 32; i++) t += s_red[i];
        int bidx = (blockIdx.z * GY + blockIdx.y) * GX + blockIdx.x;
        g_partials[bidx] = t;
        __threadfence();
        unsigned v = atomicAdd(&g_count, 1u);
        s_flag = (v == (unsigned)(NBLOCKS - 1));
    }
    __syncthreads();

    if (s_flag) {
        // deterministic: fixed summation order independent of which block runs this
        float acc = 0.f;
        for (int i = tid; i < NBLOCKS; i += NTHREADS)
            acc += __ldcg(&g_partials[i]);
        #pragma unroll
        for (int off = 16; off > 0; off >>= 1)
            acc += __shfl_down_sync(0xffffffffu, acc, off);
        if (lane == 0) s_red[warp] = acc;
        __syncthreads();
        if (tid == 0) {
            float tt = 0.f;
            #pragma unroll
            for (int i = 0; i < NTHREADS / 32; i++) tt += s_red[i];
            float mean = tt * (1.0f / ((float)BATCH * OUT_H * OUT_W));
            out[0] = (1.0f - mean) * 0.5f;
            g_count = 0;   // reset for next graph replay
        }
    }
}

extern "C" void kernel_launch(void* const* d_in, const int* in_sizes, int n_in,
                              void* d_out, int out_size)
{
    const float* img1 = (const float*)d_in[0];
    const float* img2 = (const float*)d_in[1];
    float* out = (float*)d_out;

    size_t smem_bytes = (size_t)(2 * IN_H * IN_W_PAD) * sizeof(float)
                      + (size_t)(IN_H * MID_W) * sizeof(float4);
    cudaFuncSetAttribute(ssim_tile_kernel,
                         cudaFuncAttributeMaxDynamicSharedMemorySize,
                         (int)smem_bytes);

    dim3 grid(GX, GY, BATCH);
    ssim_tile_kernel<<<grid, NTHREADS, smem_bytes>>>(img1, img2, out);
}

// round 13
// speedup vs baseline: 1.1374x; 1.0056x over previous
#include <cuda_runtime.h>

// Problem constants
#define BATCH 32
#define IMG_H 480
#define IMG_W 640
#define OUT_H 470
#define OUT_W 630
#define WS    11

// Tiling: 32 wide x 120 tall (4 row-bands cover 480 exactly)
#define TILE_W 32
#define TILE_H 120
#define IN_W   (TILE_W + WS - 1)   // 42
#define IN_W_PAD 44                // multiple of 4 for float4 loads
#define IN_H   (TILE_H + WS - 1)   // 130
#define MID_W  TILE_W              // 32

#define GX 20   // ceil(630/32)
#define GY 4    // 4 * 120 = 480 rows
#define NBLOCKS (GX * GY * BATCH)  // 2560
#define NTHREADS 640

#define H3 6                                 // stage-3 strip height
#define N_STRIPS3 ((TILE_H / H3) * TILE_W)   // 640 strips == NTHREADS exactly

// Normalized 1D Gaussian, sigma=1.5, ws=11 (symmetric)
static __device__ __forceinline__ float gw(int t) {
    constexpr float w[11] = {
        0.00102839f, 0.00759866f, 0.03600077f, 0.10936124f, 0.21300553f,
        0.26601172f,
        0.21300553f, 0.10936124f, 0.03600077f, 0.00759866f, 0.00102839f
    };
    return w[t];
}

__device__ float        g_partials[NBLOCKS];
__device__ unsigned int g_count = 0;

__global__ __launch_bounds__(NTHREADS, 2)
void ssim_tile_kernel(const float* __restrict__ img1,
                      const float* __restrict__ img2,
                      float* __restrict__ out)
{
    extern __shared__ float smem[];
    // Separate s/d arrays: stage-2 lane access is consecutive 16B -> conflict-free
    float*  s_s   = smem;                                  // IN_H * IN_W_PAD  (x+y)
    float*  s_d   = s_s + IN_H * IN_W_PAD;                 // IN_H * IN_W_PAD  (x-y)
    float4* s_mid = (float4*)(s_d + IN_H * IN_W_PAD);      // IN_H * MID_W (Ms,Md,Es,Ed)

    __shared__ float    s_red[NTHREADS / 32];
    __shared__ unsigned s_flag;

    const int tid = threadIdx.x;
    const int bz  = blockIdx.z;
    const int r0  = blockIdx.y * TILE_H;
    const int c0  = blockIdx.x * TILE_W;

    const float* im1 = img1 + (size_t)bz * IMG_H * IMG_W;
    const float* im2 = img2 + (size_t)bz * IMG_H * IMG_W;

    // ---- Stage 1: load tile (with halo), store s=x+y, d=x-y ----
    if (c0 + IN_W_PAD <= IMG_W) {
        // quad path: full-width rows (c0 mult of 32, IMG_W mult of 4 -> 16B aligned);
        // bottom-band blocks get per-row guard, OOB rows -> 0
        const int NQ = IN_W_PAD / 4;   // 11 quads per row
        for (int i = tid; i < IN_H * NQ; i += NTHREADS) {
            int r = i / NQ;
            int q = i - r * NQ;
            int gr = r0 + r;
            float4 a = make_float4(0.f, 0.f, 0.f, 0.f);
            float4 b = a;
            if (gr < IMG_H) {
                a = ((const float4*)(im1 + (size_t)gr * IMG_W + c0))[q];
                b = ((const float4*)(im2 + (size_t)gr * IMG_W + c0))[q];
            }
            float4 sv = make_float4(a.x + b.x, a.y + b.y, a.z + b.z, a.w + b.w);
            float4 dv = make_float4(a.x - b.x, a.y - b.y, a.z - b.z, a.w - b.w);
            ((float4*)(s_s + r * IN_W_PAD))[q] = sv;
            ((float4*)(s_d + r * IN_W_PAD))[q] = dv;
        }
    } else {
        // right-edge blocks (bx = GX-1): scalar guarded path
        for (int i = tid; i < IN_H * IN_W_PAD; i += NTHREADS) {
            int r = i / IN_W_PAD;
            int c = i - r * IN_W_PAD;
            int gr = r0 + r;
            int gc = c0 + c;
            float v1 = 0.f, v2 = 0.f;
            if (gr < IMG_H && gc < IMG_W) {
                int idx = gr * IMG_W + gc;
                v1 = im1[idx];
                v2 = im2[idx];
            }
            s_s[r * IN_W_PAD + c] = v1 + v2;
            s_d[r * IN_W_PAD + c] = v1 - v2;
        }
    }
    __syncthreads();

    // ---- Stage 2: horizontal conv, 4 channels (s, d, s^2, d^2), 4-wide strips ----
    // 1040 strips (130 rows x 8 quads); float4 smem loads (cq mult of 4).
    for (int st = tid; st < IN_H * (TILE_W / 4); st += NTHREADS) {
        int row = st >> 3;            // st / 8
        int cq  = (st & 7) << 2;      // (st % 8) * 4

        const float4* ps4 = (const float4*)(s_s + row * IN_W_PAD + cq);
        const float4* pd4 = (const float4*)(s_d + row * IN_W_PAD + cq);
        float sv[16], dv[16];
        #pragma unroll
        for (int i = 0; i < 4; i++) {
            float4 a = ps4[i];
            float4 b = pd4[i];
            sv[4*i+0] = a.x; sv[4*i+1] = a.y; sv[4*i+2] = a.z; sv[4*i+3] = a.w;
            dv[4*i+0] = b.x; dv[4*i+1] = b.y; dv[4*i+2] = b.z; dv[4*i+3] = b.w;
        }

        float aMs[4] = {0.f, 0.f, 0.f, 0.f};
        float aMd[4] = {0.f, 0.f, 0.f, 0.f};
        float aEs[4] = {0.f, 0.f, 0.f, 0.f};
        float aEd[4] = {0.f, 0.f, 0.f, 0.f};

        #pragma unroll
        for (int k = 0; k < WS + 3; k++) {   // 14 taps serve 4 outputs
            float skv = sv[k];
            float dkv = dv[k];
            float ss  = skv * skv;
            float dd  = dkv * dkv;
            #pragma unroll
            for (int o = 0; o < 4; o++) {
                int t = k - o;
                if (t >= 0 && t < WS) {      // compile-time resolved
                    float w = gw(t);         // literal -> FFMA-imm (rt=1)
                    aMs[o] = fmaf(w, skv, aMs[o]);
                    aMd[o] = fmaf(w, dkv, aMd[o]);
                    aEs[o] = fmaf(w, ss,  aEs[o]);
                    aEd[o] = fmaf(w, dd,  aEd[o]);
                }
            }
        }
        float4* m = s_mid + row * MID_W + cq;
        #pragma unroll
        for (int o = 0; o < 4; o++)
            m[o] = make_float4(aMs[o], aMd[o], aEs[o], aEd[o]);  // STS.128
    }
    __syncthreads();

    // ---- Stage 3: vertical conv + SSIM + local sum; 6-tall strips ----
    // 640 strips == 640 threads: 16 taps serve 6 outputs (2.67 LDS.128/output).
    const float C1 = 1.0f;   // (0.01*100)^2
    const float C2 = 9.0f;   // (0.03*100)^2
    float lsum = 0.f;

    {
        int c  = tid & (TILE_W - 1);
        int rq = (tid >> 5) * H3;

        float Ms[H3] = {0.f, 0.f, 0.f, 0.f, 0.f, 0.f};
        float Md[H3] = {0.f, 0.f, 0.f, 0.f, 0.f, 0.f};
        float Es[H3] = {0.f, 0.f, 0.f, 0.f, 0.f, 0.f};
        float Ed[H3] = {0.f, 0.f, 0.f, 0.f, 0.f, 0.f};

        #pragma unroll
        for (int k = 0; k < WS + H3 - 1; k++) {   // 16 taps
            float4 v = s_mid[(rq + k) * MID_W + c];   // one LDS.128 per tap
            #pragma unroll
            for (int o = 0; o < H3; o++) {
                int t = k - o;
                if (t >= 0 && t < WS) {
                    float w = gw(t);
                    Ms[o] = fmaf(w, v.x, Ms[o]);
                    Md[o] = fmaf(w, v.y, Md[o]);
                    Es[o] = fmaf(w, v.z, Es[o]);
                    Ed[o] = fmaf(w, v.w, Ed[o]);
                }
            }
        }

        int gc = c0 + c;
        if (gc < OUT_W) {
            #pragma unroll
            for (int o = 0; o < H3; o++) {
                int gr = r0 + rq + o;
                if (gr < OUT_H) {
                    float ms = Ms[o], md = Md[o];
                    float ms2 = ms * ms;
                    float md2 = md * md;
                    float Ps = Es[o] - ms2;     // s1+s2+2*s12
                    float Qd = Ed[o] - md2;     // s1+s2-2*s12
                    float v1 = 0.5f * (Ps - Qd) + C2;            // 2*s12 + C2
                    float v2 = 0.5f * (Ps + Qd) + C2;            // s1+s2 + C2
                    float num = (0.5f * (ms2 - md2) + C1) * v1;  // (2*mu12+C1)*v1
                    float den = (0.5f * (ms2 + md2) + C1) * v2;  // (mu1^2+mu2^2+C1)*v2
                    lsum += __fdividef(num, den);
                }
            }
        }
    }

    // ---- Stage 4: block partial + fused last-block finalize ----
    #pragma unroll
    for (int off = 16; off > 0; off >>= 1)
        lsum += __shfl_down_sync(0xffffffffu, lsum, off);

    int warp = tid >> 5;
    int lane = tid & 31;
    if (lane == 0) s_red[warp] = lsum;
    __syncthreads();
    if (tid == 0) {
        float t = 0.f;
        #pragma unroll
        for (int i = 0; i < NTHREADS / 32; i++) t += s_red[i];
        int bidx = (blockIdx.z * GY + blockIdx.y) * GX + blockIdx.x;
        g_partials[bidx] = t;
        __threadfence();
        unsigned v = atomicAdd(&g_count, 1u);
        s_flag = (v == (unsigned)(NBLOCKS - 1));
    }
    __syncthreads();

    if (s_flag) {
        // deterministic: fixed summation order independent of which block runs this
        float acc = 0.f;
        for (int i = tid; i < NBLOCKS; i += NTHREADS)
            acc += __ldcg(&g_partials[i]);
        #pragma unroll
        for (int off = 16; off > 0; off >>= 1)
            acc += __shfl_down_sync(0xffffffffu, acc, off);
        if (lane == 0) s_red[warp] = acc;
        __syncthreads();
        if (tid == 0) {
            float tt = 0.f;
            #pragma unroll
            for (int i = 0; i < NTHREADS / 32; i++) tt += s_red[i];
            float mean = tt * (1.0f / ((float)BATCH * OUT_H * OUT_W));
            out[0] = (1.0f - mean) * 0.5f;
            g_count = 0;   // reset for next graph replay
        }
    }
}

extern "C" void kernel_launch(void* const* d_in, const int* in_sizes, int n_in,
                              void* d_out, int out_size)
{
    const float* img1 = (const float*)d_in[0];
    const float* img2 = (const float*)d_in[1];
    float* out = (float*)d_out;

    size_t smem_bytes = (size_t)(2 * IN_H * IN_W_PAD) * sizeof(float)
                      + (size_t)(IN_H * MID_W) * sizeof(float4);
    cudaFuncSetAttribute(ssim_tile_kernel,
                         cudaFuncAttributeMaxDynamicSharedMemorySize,
                         (int)smem_bytes);

    dim3 grid(GX, GY, BATCH);
    ssim_tile_kernel<<<grid, NTHREADS, smem_bytes>>>(img1, img2, out);
}

// round 14
// speedup vs baseline: 1.3707x; 1.2051x over previous
#include <cuda_runtime.h>
#include <cuda_fp16.h>

// Problem constants
#define BATCH 32
#define IMG_H 480
#define IMG_W 640
#define OUT_H 470
#define OUT_W 630
#define WS    11

// Tiling: 32 wide x 120 tall (4 row-bands cover 480 exactly)
#define TILE_W 32
#define TILE_H 120
#define IN_W   (TILE_W + WS - 1)   // 42
#define IN_W_PAD 44                // multiple of 4 for float4 loads
#define IN_H   (TILE_H + WS - 1)   // 130
#define MID_W  TILE_W              // 32

#define GX 20   // ceil(630/32)
#define GY 4    // 4 * 120 = 480 rows
#define NBLOCKS (GX * GY * BATCH)  // 2560
#define NTHREADS 640

#define H3 6                                 // stage-3 strip height
#define N_STRIPS3 ((TILE_H / H3) * TILE_W)   // 640 strips == NTHREADS exactly

// Normalized 1D Gaussian, sigma=1.5, ws=11 (symmetric)
static __device__ __forceinline__ float gw(int t) {
    constexpr float w[11] = {
        0.00102839f, 0.00759866f, 0.03600077f, 0.10936124f, 0.21300553f,
        0.26601172f,
        0.21300553f, 0.10936124f, 0.03600077f, 0.00759866f, 0.00102839f
    };
    return w[t];
}

static __device__ __forceinline__ unsigned h2u(__half2 h) { return *(unsigned*)&h; }
static __device__ __forceinline__ __half2  u2h(unsigned u) { return *(__half2*)&u; }

__device__ float        g_partials[NBLOCKS];
__device__ unsigned int g_count = 0;

__global__ __launch_bounds__(NTHREADS, 2)
void ssim_tile_kernel(const float* __restrict__ img1,
                      const float* __restrict__ img2,
                      float* __restrict__ out)
{
    extern __shared__ float smem[];
    // Separate s/d arrays: stage-2 lane access is consecutive 16B -> conflict-free
    float* s_s   = smem;                                  // IN_H * IN_W_PAD  (x+y)
    float* s_d   = s_s + IN_H * IN_W_PAD;                 // IN_H * IN_W_PAD  (x-y)
    uint2* s_mid = (uint2*)(s_d + IN_H * IN_W_PAD);       // IN_H*MID_W: (h2(Ms,Md), h2(Es,Ed))

    __shared__ float    s_red[NTHREADS / 32];
    __shared__ unsigned s_flag;

    const int tid = threadIdx.x;
    const int bz  = blockIdx.z;
    const int r0  = blockIdx.y * TILE_H;
    const int c0  = blockIdx.x * TILE_W;

    const float* im1 = img1 + (size_t)bz * IMG_H * IMG_W;
    const float* im2 = img2 + (size_t)bz * IMG_H * IMG_W;

    // ---- Stage 1: load tile (with halo), store s=x+y, d=x-y ----
    if (c0 + IN_W_PAD <= IMG_W) {
        // quad path: full-width rows (c0 mult of 32, IMG_W mult of 4 -> 16B aligned);
        // bottom-band blocks get per-row guard, OOB rows -> 0
        const int NQ = IN_W_PAD / 4;   // 11 quads per row
        for (int i = tid; i < IN_H * NQ; i += NTHREADS) {
            int r = i / NQ;
            int q = i - r * NQ;
            int gr = r0 + r;
            float4 a = make_float4(0.f, 0.f, 0.f, 0.f);
            float4 b = a;
            if (gr < IMG_H) {
                a = ((const float4*)(im1 + (size_t)gr * IMG_W + c0))[q];
                b = ((const float4*)(im2 + (size_t)gr * IMG_W + c0))[q];
            }
            float4 sv = make_float4(a.x + b.x, a.y + b.y, a.z + b.z, a.w + b.w);
            float4 dv = make_float4(a.x - b.x, a.y - b.y, a.z - b.z, a.w - b.w);
            ((float4*)(s_s + r * IN_W_PAD))[q] = sv;
            ((float4*)(s_d + r * IN_W_PAD))[q] = dv;
        }
    } else {
        // right-edge blocks (bx = GX-1): scalar guarded path
        for (int i = tid; i < IN_H * IN_W_PAD; i += NTHREADS) {
            int r = i / IN_W_PAD;
            int c = i - r * IN_W_PAD;
            int gr = r0 + r;
            int gc = c0 + c;
            float v1 = 0.f, v2 = 0.f;
            if (gr < IMG_H && gc < IMG_W) {
                int idx = gr * IMG_W + gc;
                v1 = im1[idx];
                v2 = im2[idx];
            }
            s_s[r * IN_W_PAD + c] = v1 + v2;
            s_d[r * IN_W_PAD + c] = v1 - v2;
        }
    }
    __syncthreads();

    // ---- Stage 2: horizontal conv (fp32), 4 channels, 4-wide strips; half2 store ----
    for (int st = tid; st < IN_H * (TILE_W / 4); st += NTHREADS) {
        int row = st >> 3;            // st / 8
        int cq  = (st & 7) << 2;      // (st % 8) * 4

        const float4* ps4 = (const float4*)(s_s + row * IN_W_PAD + cq);
        const float4* pd4 = (const float4*)(s_d + row * IN_W_PAD + cq);
        float sv[16], dv[16];
        #pragma unroll
        for (int i = 0; i < 4; i++) {
            float4 a = ps4[i];
            float4 b = pd4[i];
            sv[4*i+0] = a.x; sv[4*i+1] = a.y; sv[4*i+2] = a.z; sv[4*i+3] = a.w;
            dv[4*i+0] = b.x; dv[4*i+1] = b.y; dv[4*i+2] = b.z; dv[4*i+3] = b.w;
        }

        float aMs[4] = {0.f, 0.f, 0.f, 0.f};
        float aMd[4] = {0.f, 0.f, 0.f, 0.f};
        float aEs[4] = {0.f, 0.f, 0.f, 0.f};
        float aEd[4] = {0.f, 0.f, 0.f, 0.f};

        #pragma unroll
        for (int k = 0; k < WS + 3; k++) {   // 14 taps serve 4 outputs
            float skv = sv[k];
            float dkv = dv[k];
            float ss  = skv * skv;
            float dd  = dkv * dkv;
            #pragma unroll
            for (int o = 0; o < 4; o++) {
                int t = k - o;
                if (t >= 0 && t < WS) {      // compile-time resolved
                    float w = gw(t);         // literal -> FFMA-imm (rt=1)
                    aMs[o] = fmaf(w, skv, aMs[o]);
                    aMd[o] = fmaf(w, dkv, aMd[o]);
                    aEs[o] = fmaf(w, ss,  aEs[o]);
                    aEd[o] = fmaf(w, dd,  aEd[o]);
                }
            }
        }
        // pack to half2 pairs; 2 x STS.128 (lane-consecutive 16B, conflict-free)
        __half2 hM0 = __floats2half2_rn(aMs[0], aMd[0]);
        __half2 hE0 = __floats2half2_rn(aEs[0], aEd[0]);
        __half2 hM1 = __floats2half2_rn(aMs[1], aMd[1]);
        __half2 hE1 = __floats2half2_rn(aEs[1], aEd[1]);
        __half2 hM2 = __floats2half2_rn(aMs[2], aMd[2]);
        __half2 hE2 = __floats2half2_rn(aEs[2], aEd[2]);
        __half2 hM3 = __floats2half2_rn(aMs[3], aMd[3]);
        __half2 hE3 = __floats2half2_rn(aEs[3], aEd[3]);
        uint4* m4 = (uint4*)(s_mid + row * MID_W + cq);
        m4[0] = make_uint4(h2u(hM0), h2u(hE0), h2u(hM1), h2u(hE1));
        m4[1] = make_uint4(h2u(hM2), h2u(hE2), h2u(hM3), h2u(hE3));
    }
    __syncthreads();

    // ---- Stage 3: vertical conv in half2 (HFMA2) + fp32 SSIM epilogue ----
    // 640 strips == 640 threads; 16 taps serve 6 outputs; 1 LDS.64 per tap.
    const float C1 = 1.0f;   // (0.01*100)^2
    const float C2 = 9.0f;   // (0.03*100)^2
    float lsum = 0.f;

    {
        int c  = tid & (TILE_W - 1);
        int rq = (tid >> 5) * H3;

        __half2 wh[WS];
        #pragma unroll
        for (int t = 0; t < WS; t++)
            wh[t] = __floats2half2_rn(gw(t), gw(t));

        __half2 accM[H3], accE[H3];
        #pragma unroll
        for (int o = 0; o < H3; o++) {
            accM[o] = __floats2half2_rn(0.f, 0.f);
            accE[o] = __floats2half2_rn(0.f, 0.f);
        }

        #pragma unroll
        for (int k = 0; k < WS + H3 - 1; k++) {   // 16 taps
            uint2 u = s_mid[(rq + k) * MID_W + c];   // LDS.64, conflict-free
            __half2 vm = u2h(u.x);
            __half2 ve = u2h(u.y);
            #pragma unroll
            for (int o = 0; o < H3; o++) {
                int t = k - o;
                if (t >= 0 && t < WS) {
                    accM[o] = __hfma2(wh[t], vm, accM[o]);
                    accE[o] = __hfma2(wh[t], ve, accE[o]);
                }
            }
        }

        int gc = c0 + c;
        if (gc < OUT_W) {
            #pragma unroll
            for (int o = 0; o < H3; o++) {
                int gr = r0 + rq + o;
                if (gr < OUT_H) {
                    float2 M = __half22float2(accM[o]);
                    float2 E = __half22float2(accE[o]);
                    float ms = M.x, md = M.y;
                    float ms2 = ms * ms;
                    float md2 = md * md;
                    float Ps = E.x - ms2;     // s1+s2+2*s12
                    float Qd = E.y - md2;     // s1+s2-2*s12
                    float v1 = 0.5f * (Ps - Qd) + C2;            // 2*s12 + C2
                    float v2 = 0.5f * (Ps + Qd) + C2;            // s1+s2 + C2
                    float num = (0.5f * (ms2 - md2) + C1) * v1;  // (2*mu12+C1)*v1
                    float den = (0.5f * (ms2 + md2) + C1) * v2;  // (mu1^2+mu2^2+C1)*v2
                    lsum += __fdividef(num, den);
                }
            }
        }
    }

    // ---- Stage 4: block partial + fused last-block finalize ----
    #pragma unroll
    for (int off = 16; off > 0; off >>= 1)
        lsum += __shfl_down_sync(0xffffffffu, lsum, off);

    int warp = tid >> 5;
    int lane = tid & 31;
    if (lane == 0) s_red[warp] = lsum;
    __syncthreads();
    if (tid == 0) {
        float t = 0.f;
        #pragma unroll
        for (int i = 0; i < NTHREADS / 32; i++) t += s_red[i];
        int bidx = (blockIdx.z * GY + blockIdx.y) * GX + blockIdx.x;
        g_partials[bidx] = t;
        __threadfence();
        unsigned v = atomicAdd(&g_count, 1u);
        s_flag = (v == (unsigned)(NBLOCKS - 1));
    }
    __syncthreads();

    if (s_flag) {
        // deterministic: fixed summation order independent of which block runs this
        float acc = 0.f;
        for (int i = tid; i < NBLOCKS; i += NTHREADS)
            acc += __ldcg(&g_partials[i]);
        #pragma unroll
        for (int off = 16; off > 0; off >>= 1)
            acc += __shfl_down_sync(0xffffffffu, acc, off);
        if (lane == 0) s_red[warp] = acc;
        __syncthreads();
        if (tid == 0) {
            float tt = 0.f;
            #pragma unroll
            for (int i = 0; i < NTHREADS / 32; i++) tt += s_red[i];
            float mean = tt * (1.0f / ((float)BATCH * OUT_H * OUT_W));
            out[0] = (1.0f - mean) * 0.5f;
            g_count = 0;   // reset for next graph replay
        }
    }
}

extern "C" void kernel_launch(void* const* d_in, const int* in_sizes, int n_in,
                              void* d_out, int out_size)
{
    const float* img1 = (const float*)d_in[0];
    const float* img2 = (const float*)d_in[1];
    float* out = (float*)d_out;

    size_t smem_bytes = (size_t)(2 * IN_H * IN_W_PAD) * sizeof(float)
                      + (size_t)(IN_H * MID_W) * sizeof(uint2);
    cudaFuncSetAttribute(ssim_tile_kernel,
                         cudaFuncAttributeMaxDynamicSharedMemorySize,
                         (int)smem_bytes);

    dim3 grid(GX, GY, BATCH);
    ssim_tile_kernel<<<grid, NTHREADS, smem_bytes>>>(img1, img2, out);
}

// round 15
// speedup vs baseline: 1.4207x; 1.0365x over previous
#include <cuda_runtime.h>
#include <cuda_fp16.h>

// Problem constants
#define BATCH 32
#define IMG_H 480
#define IMG_W 640
#define OUT_H 470
#define OUT_W 630
#define WS    11

// Tiling: 32 wide x 120 tall (4 row-bands cover 480 exactly)
#define TILE_W 32
#define TILE_H 120
#define IN_W   (TILE_W + WS - 1)   // 42
#define IN_W_PAD 44                // multiple of 4 for vector loads
#define IN_H   (TILE_H + WS - 1)   // 130
#define MID_W  TILE_W              // 32

#define GX 20   // ceil(630/32)
#define GY 4    // 4 * 120 = 480 rows
#define NBLOCKS (GX * GY * BATCH)  // 2560
#define NTHREADS 640

#define H3 6                                 // stage-3 strip height
#define N_STRIPS3 ((TILE_H / H3) * TILE_W)   // 640 strips == NTHREADS exactly

// Normalized 1D Gaussian, sigma=1.5, ws=11 (symmetric)
static __device__ __forceinline__ float gw(int t) {
    constexpr float w[11] = {
        0.00102839f, 0.00759866f, 0.03600077f, 0.10936124f, 0.21300553f,
        0.26601172f,
        0.21300553f, 0.10936124f, 0.03600077f, 0.00759866f, 0.00102839f
    };
    return w[t];
}

static __device__ __forceinline__ unsigned h2u(__half2 h) { return *(unsigned*)&h; }
static __device__ __forceinline__ __half2  u2h(unsigned u) { return *(__half2*)&u; }

__device__ float        g_partials[NBLOCKS];
__device__ unsigned int g_count = 0;

__global__ __launch_bounds__(NTHREADS, 2)
void ssim_tile_kernel(const float* __restrict__ img1,
                      const float* __restrict__ img2,
                      float* __restrict__ out)
{
    extern __shared__ float smem[];
    // s_sd: packed half2(s,d) per pixel. 4B/px.
    unsigned* s_sd  = (unsigned*)smem;                    // IN_H * IN_W_PAD
    uint2*    s_mid = (uint2*)(s_sd + IN_H * IN_W_PAD);   // IN_H*MID_W: (h2(Ms,Md), h2(Es,Ed))

    __shared__ float    s_red[NTHREADS / 32];
    __shared__ unsigned s_flag;

    const int tid = threadIdx.x;
    const int bz  = blockIdx.z;
    const int r0  = blockIdx.y * TILE_H;
    const int c0  = blockIdx.x * TILE_W;

    const float* im1 = img1 + (size_t)bz * IMG_H * IMG_W;
    const float* im2 = img2 + (size_t)bz * IMG_H * IMG_W;

    // ---- Stage 1: load tile (with halo), store packed half2(s, d) ----
    if (c0 + IN_W_PAD <= IMG_W) {
        // quad path: full-width rows (c0 mult of 32, IMG_W mult of 4 -> 16B aligned);
        // bottom-band blocks get per-row guard, OOB rows -> 0
        const int NQ = IN_W_PAD / 4;   // 11 quads per row
        for (int i = tid; i < IN_H * NQ; i += NTHREADS) {
            int r = i / NQ;
            int q = i - r * NQ;
            int gr = r0 + r;
            float4 a = make_float4(0.f, 0.f, 0.f, 0.f);
            float4 b = a;
            if (gr < IMG_H) {
                a = ((const float4*)(im1 + (size_t)gr * IMG_W + c0))[q];
                b = ((const float4*)(im2 + (size_t)gr * IMG_W + c0))[q];
            }
            uint4 packed;
            packed.x = h2u(__floats2half2_rn(a.x + b.x, a.x - b.x));
            packed.y = h2u(__floats2half2_rn(a.y + b.y, a.y - b.y));
            packed.z = h2u(__floats2half2_rn(a.z + b.z, a.z - b.z));
            packed.w = h2u(__floats2half2_rn(a.w + b.w, a.w - b.w));
            ((uint4*)(s_sd + r * IN_W_PAD))[q] = packed;   // STS.128
        }
    } else {
        // right-edge blocks (bx = GX-1): scalar guarded path
        for (int i = tid; i < IN_H * IN_W_PAD; i += NTHREADS) {
            int r = i / IN_W_PAD;
            int c = i - r * IN_W_PAD;
            int gr = r0 + r;
            int gc = c0 + c;
            float v1 = 0.f, v2 = 0.f;
            if (gr < IMG_H && gc < IMG_W) {
                int idx = gr * IMG_W + gc;
                v1 = im1[idx];
                v2 = im2[idx];
            }
            s_sd[r * IN_W_PAD + c] = h2u(__floats2half2_rn(v1 + v2, v1 - v2));
        }
    }
    __syncthreads();

    // ---- Stage 2: horizontal conv in half2 (HFMA2), 4-wide strips ----
    // 1040 strips (130 rows x 8 quads); 4 x LDS.128 per strip (lane-distinct 16B).
    {
        __half2 wh[WS];
        #pragma unroll
        for (int t = 0; t < WS; t++)
            wh[t] = __floats2half2_rn(gw(t), gw(t));

        for (int st = tid; st < IN_H * (TILE_W / 4); st += NTHREADS) {
            int row = st >> 3;            // st / 8
            int cq  = (st & 7) << 2;      // (st % 8) * 4

            // 16 packed (s,d) half2; taps use first 14
            const uint4* p4 = (const uint4*)(s_sd + row * IN_W_PAD + cq);
            unsigned pv[16];
            #pragma unroll
            for (int i = 0; i < 4; i++) {
                uint4 u = p4[i];
                pv[4*i+0] = u.x; pv[4*i+1] = u.y; pv[4*i+2] = u.z; pv[4*i+3] = u.w;
            }

            __half2 aM[4], aE[4];
            #pragma unroll
            for (int o = 0; o < 4; o++) {
                aM[o] = __floats2half2_rn(0.f, 0.f);
                aE[o] = __floats2half2_rn(0.f, 0.f);
            }

            #pragma unroll
            for (int k = 0; k < WS + 3; k++) {   // 14 taps serve 4 outputs
                __half2 pk  = u2h(pv[k]);        // (s, d)
                __half2 psq = __hmul2(pk, pk);   // (s^2, d^2)
                #pragma unroll
                for (int o = 0; o < 4; o++) {
                    int t = k - o;
                    if (t >= 0 && t < WS) {      // compile-time resolved
                        aM[o] = __hfma2(wh[t], pk,  aM[o]);
                        aE[o] = __hfma2(wh[t], psq, aE[o]);
                    }
                }
            }
            // accumulators are already the mid format: 2 x STS.128, no cvt
            uint4* m4 = (uint4*)(s_mid + row * MID_W + cq);
            m4[0] = make_uint4(h2u(aM[0]), h2u(aE[0]), h2u(aM[1]), h2u(aE[1]));
            m4[1] = make_uint4(h2u(aM[2]), h2u(aE[2]), h2u(aM[3]), h2u(aE[3]));
        }
    }
    __syncthreads();

    // ---- Stage 3: vertical conv in half2 (HFMA2) + fp32 SSIM epilogue ----
    // 640 strips == 640 threads; 16 taps serve 6 outputs; 1 LDS.64 per tap.
    const float C1 = 1.0f;   // (0.01*100)^2
    const float C2 = 9.0f;   // (0.03*100)^2
    float lsum = 0.f;

    {
        int c  = tid & (TILE_W - 1);
        int rq = (tid >> 5) * H3;

        __half2 wh[WS];
        #pragma unroll
        for (int t = 0; t < WS; t++)
            wh[t] = __floats2half2_rn(gw(t), gw(t));

        __half2 accM[H3], accE[H3];
        #pragma unroll
        for (int o = 0; o < H3; o++) {
            accM[o] = __floats2half2_rn(0.f, 0.f);
            accE[o] = __floats2half2_rn(0.f, 0.f);
        }

        #pragma unroll
        for (int k = 0; k < WS + H3 - 1; k++) {   // 16 taps
            uint2 u = s_mid[(rq + k) * MID_W + c];   // LDS.64, conflict-free
            __half2 vm = u2h(u.x);
            __half2 ve = u2h(u.y);
            #pragma unroll
            for (int o = 0; o < H3; o++) {
                int t = k - o;
                if (t >= 0 && t < WS) {
                    accM[o] = __hfma2(wh[t], vm, accM[o]);
                    accE[o] = __hfma2(wh[t], ve, accE[o]);
                }
            }
        }

        int gc = c0 + c;
        if (gc < OUT_W) {
            #pragma unroll
            for (int o = 0; o < H3; o++) {
                int gr = r0 + rq + o;
                if (gr < OUT_H) {
                    float2 M = __half22float2(accM[o]);
                    float2 E = __half22float2(accE[o]);
                    float ms = M.x, md = M.y;
                    float ms2 = ms * ms;
                    float md2 = md * md;
                    float Ps = E.x - ms2;     // s1+s2+2*s12
                    float Qd = E.y - md2;     // s1+s2-2*s12
                    float v1 = 0.5f * (Ps - Qd) + C2;            // 2*s12 + C2
                    float v2 = 0.5f * (Ps + Qd) + C2;            // s1+s2 + C2
                    float num = (0.5f * (ms2 - md2) + C1) * v1;  // (2*mu12+C1)*v1
                    float den = (0.5f * (ms2 + md2) + C1) * v2;  // (mu1^2+mu2^2+C1)*v2
                    lsum += __fdividef(num, den);
                }
            }
        }
    }

    // ---- Stage 4: block partial + fused last-block finalize ----
    #pragma unroll
    for (int off = 16; off > 0; off >>= 1)
        lsum += __shfl_down_sync(0xffffffffu, lsum, off);

    int warp = tid >> 5;
    int lane = tid & 31;
    if (lane == 0) s_red[warp] = lsum;
    __syncthreads();
    if (tid == 0) {
        float t = 0.f;
        #pragma unroll
        for (int i = 0; i < NTHREADS / 32; i++) t += s_red[i];
        int bidx = (blockIdx.z * GY + blockIdx.y) * GX + blockIdx.x;
        g_partials[bidx] = t;
        __threadfence();
        unsigned v = atomicAdd(&g_count, 1u);
        s_flag = (v == (unsigned)(NBLOCKS - 1));
    }
    __syncthreads();

    if (s_flag) {
        // deterministic: fixed summation order independent of which block runs this
        float acc = 0.f;
        for (int i = tid; i < NBLOCKS; i += NTHREADS)
            acc += __ldcg(&g_partials[i]);
        #pragma unroll
        for (int off = 16; off > 0; off >>= 1)
            acc += __shfl_down_sync(0xffffffffu, acc, off);
        if (lane == 0) s_red[warp] = acc;
        __syncthreads();
        if (tid == 0) {
            float tt = 0.f;
            #pragma unroll
            for (int i = 0; i < NTHREADS / 32; i++) tt += s_red[i];
            float mean = tt * (1.0f / ((float)BATCH * OUT_H * OUT_W));
            out[0] = (1.0f - mean) * 0.5f;
            g_count = 0;   // reset for next graph replay
        }
    }
}

extern "C" void kernel_launch(void* const* d_in, const int* in_sizes, int n_in,
                              void* d_out, int out_size)
{
    const float* img1 = (const float*)d_in[0];
    const float* img2 = (const float*)d_in[1];
    float* out = (float*)d_out;

    size_t smem_bytes = (size_t)(IN_H * IN_W_PAD) * sizeof(unsigned)
                      + (size_t)(IN_H * MID_W) * sizeof(uint2);
    cudaFuncSetAttribute(ssim_tile_kernel,
                         cudaFuncAttributeMaxDynamicSharedMemorySize,
                         (int)smem_bytes);

    dim3 grid(GX, GY, BATCH);
    ssim_tile_kernel<<<grid, NTHREADS, smem_bytes>>>(img1, img2, out);
}